// round 3
// baseline (speedup 1.0000x reference)
#include <cuda_runtime.h>
#include <math.h>

#define BB     8
#define NFULL  8192
#define NPART  2048
#define DLAT   512
#define EPSV   1e-12f

__device__ float g_pf[BB * NFULL];
__device__ float g_fp[BB * NFULL];
__device__ float g_part[BB * NPART];

constexpr int THREADS = 256;
constexpr int Q       = 4;                // queries per thread
constexpr int QPB     = THREADS * Q;      // 1024
constexpr int CHUNK   = 2048;             // ref points per tile
constexpr int CH2     = CHUNK / 2;        // packed ref pairs per tile

typedef unsigned long long u64;

__device__ __forceinline__ u64 pack2(float lo, float hi) {
    u64 r; asm("mov.b64 %0, {%1, %2};" : "=l"(r) : "f"(lo), "f"(hi)); return r;
}
__device__ __forceinline__ void unpack2(u64 v, float& lo, float& hi) {
    asm("mov.b64 {%0, %1}, %2;" : "=f"(lo), "=f"(hi) : "l"(v));
}
__device__ __forceinline__ u64 ffma2(u64 a, u64 b, u64 c) {
    u64 d; asm("fma.rn.f32x2 %0, %1, %2, %3;" : "=l"(d) : "l"(a), "l"(b), "l"(c)); return d;
}

// ---------------------------------------------------------------------------
// Fused row-min: chamfer pred->full, full->pred, fidelity partial->pred.
// For each query q: min_j( w_j - dot(q, r_j) ), w = |r|^2/2; sq = q^2 + 2*min.
// Tiles stored as pre-packed f32x2 register pairs (ulonglong2) so LDS.128
// feeds FFMA2 with zero pack/unpack MOVs.
// ---------------------------------------------------------------------------
constexpr int RCHUNKS   = NFULL / CHUNK;            // 4
constexpr int CHAM_QT   = NFULL / QPB;              // 8
constexpr int FID_QT    = NPART / QPB;              // 2
constexpr int CHAM_BLKS = CHAM_QT * RCHUNKS * BB;   // 256
constexpr int FID_BLKS  = FID_QT * RCHUNKS * BB;    // 64
constexpr int TOT_BLKS  = 2 * CHAM_BLKS + FID_BLKS; // 576

__global__ __launch_bounds__(THREADS)
void fused_rowmin_kernel(const float* __restrict__ pred,
                         const float* __restrict__ full,
                         const float* __restrict__ partial,
                         float* __restrict__ pf,
                         float* __restrict__ fp,
                         float* __restrict__ pp) {
    __shared__ ulonglong2 tA[CH2];   // (.x = pack(x0,x1), .y = pack(y0,y1))
    __shared__ ulonglong2 tB[CH2];   // (.x = pack(z0,z1), .y = pack(w0,w1))

    // ---- decode task ----
    const float *q, *r;
    float* outmin;
    int Nq, qtiles, l = blockIdx.x;
    if (l < CHAM_BLKS) {
        q = pred; r = full; outmin = pf; Nq = NFULL; qtiles = CHAM_QT;
    } else if (l < 2 * CHAM_BLKS) {
        l -= CHAM_BLKS;
        q = full; r = pred; outmin = fp; Nq = NFULL; qtiles = CHAM_QT;
    } else {
        l -= 2 * CHAM_BLKS;
        q = partial; r = pred; outmin = pp; Nq = NPART; qtiles = FID_QT;
    }
    const int b  = l / (qtiles * RCHUNKS);
    const int rm = l % (qtiles * RCHUNKS);
    const int ck = rm / qtiles;
    const int qt = rm % qtiles;
    const int qbase = qt * QPB;
    const int rbase = ck * CHUNK;

    const float* qb = q + (size_t)b * Nq * 3;
    const float* rb = r + (size_t)b * NFULL * 3;

    // ---- cooperative packed tile load ----
    for (int j = threadIdx.x; j < CH2; j += THREADS) {
        int rj = rbase + 2 * j;
        float x0 = rb[rj * 3 + 0], y0 = rb[rj * 3 + 1], z0 = rb[rj * 3 + 2];
        float x1 = rb[rj * 3 + 3], y1 = rb[rj * 3 + 4], z1 = rb[rj * 3 + 5];
        float w0 = 0.5f * (x0 * x0 + y0 * y0 + z0 * z0);
        float w1 = 0.5f * (x1 * x1 + y1 * y1 + z1 * z1);
        ulonglong2 a, bb;
        a.x  = pack2(x0, x1); a.y  = pack2(y0, y1);
        bb.x = pack2(z0, z1); bb.y = pack2(w0, w1);
        tA[j] = a;
        tB[j] = bb;
    }
    __syncthreads();

    // ---- per-thread queries (negated, broadcast-packed) ----
    u64 nqx[Q], nqy[Q], nqz[Q];
    float q2[Q], m0[Q], m1[Q];
#pragma unroll
    for (int k = 0; k < Q; k++) {
        int qi = qbase + threadIdx.x + k * THREADS;
        float x = qb[qi * 3 + 0];
        float y = qb[qi * 3 + 1];
        float z = qb[qi * 3 + 2];
        nqx[k] = pack2(-x, -x);
        nqy[k] = pack2(-y, -y);
        nqz[k] = pack2(-z, -z);
        q2[k]  = x * x + y * y + z * z;
        m0[k]  = __int_as_float(0x7f800000);
        m1[k]  = __int_as_float(0x7f800000);
    }

    // ---- main loop: 2 ref points / iteration, 3 FFMA2 + 2 FMNMX per query ----
#pragma unroll 4
    for (int j = 0; j < CH2; j++) {
        ulonglong2 A = tA[j];   // xp, yp
        ulonglong2 B = tB[j];   // zp, wp
#pragma unroll
        for (int k = 0; k < Q; k++) {
            u64 v = ffma2(nqz[k], B.x, B.y);
            v = ffma2(nqy[k], A.y, v);
            v = ffma2(nqx[k], A.x, v);
            float v0, v1;
            unpack2(v, v0, v1);
            m0[k] = fminf(m0[k], v0);
            m1[k] = fminf(m1[k], v1);
        }
    }

    // ---- writeback: sq = q2 + 2*min, clamp, atomic min-combine ----
#pragma unroll
    for (int k = 0; k < Q; k++) {
        int qi   = qbase + threadIdx.x + k * THREADS;
        float mn = fminf(m0[k], m1[k]);
        float sq = fmaf(2.0f, mn, q2[k]);
        float v  = fmaxf(sq, EPSV);
        atomicMin((unsigned int*)&outmin[(size_t)b * Nq + qi], __float_as_uint(v));
    }
}

// ---------------------------------------------------------------------------
__global__ void reduce_kernel(const float* __restrict__ pf,
                              const float* __restrict__ fp,
                              const float* __restrict__ pp,
                              const float* __restrict__ mu,
                              const float* __restrict__ lv,
                              float* __restrict__ out) {
    const int tid = threadIdx.x;
    const int nt  = blockDim.x;

    float s_pf = 0.f, s_fp = 0.f, s_pp = 0.f, s_kl = 0.f;
    for (int i = tid; i < BB * NFULL; i += nt) {
        s_pf += sqrtf(pf[i]);
        s_fp += sqrtf(fp[i]);
    }
    for (int i = tid; i < BB * NPART; i += nt) s_pp += sqrtf(pp[i]);
    for (int i = tid; i < BB * DLAT; i += nt) {
        float m = mu[i], l = lv[i];
        s_kl += 1.0f + l - m * m - expf(l);
    }

    __shared__ float sh[4][32];
#pragma unroll
    for (int off = 16; off > 0; off >>= 1) {
        s_pf += __shfl_down_sync(0xffffffffu, s_pf, off);
        s_fp += __shfl_down_sync(0xffffffffu, s_fp, off);
        s_pp += __shfl_down_sync(0xffffffffu, s_pp, off);
        s_kl += __shfl_down_sync(0xffffffffu, s_kl, off);
    }
    int wid = tid >> 5, lid = tid & 31;
    if (lid == 0) { sh[0][wid] = s_pf; sh[1][wid] = s_fp; sh[2][wid] = s_pp; sh[3][wid] = s_kl; }
    __syncthreads();

    if (wid == 0) {
        int nwarps = nt >> 5;
        float a = (lid < nwarps) ? sh[0][lid] : 0.f;
        float b = (lid < nwarps) ? sh[1][lid] : 0.f;
        float c = (lid < nwarps) ? sh[2][lid] : 0.f;
        float d = (lid < nwarps) ? sh[3][lid] : 0.f;
#pragma unroll
        for (int off = 16; off > 0; off >>= 1) {
            a += __shfl_down_sync(0xffffffffu, a, off);
            b += __shfl_down_sync(0xffffffffu, b, off);
            c += __shfl_down_sync(0xffffffffu, c, off);
            d += __shfl_down_sync(0xffffffffu, d, off);
        }
        if (lid == 0) {
            float inv_nf = 1.0f / (float)(BB * NFULL);
            float cd  = 0.5f * (a + b) * inv_nf;
            float fid = c / (float)(BB * NPART);
            float kl  = -0.5f * d / (float)BB;
            float total = 1.0f * cd + 0.01f * kl + 0.5f * fid;
            out[0] = total;
            out[1] = cd;
            out[2] = kl;
            out[3] = fid;
        }
    }
}

// ---------------------------------------------------------------------------
extern "C" void kernel_launch(void* const* d_in, const int* in_sizes, int n_in,
                              void* d_out, int out_size) {
    const float* pred    = (const float*)d_in[0];
    const float* full    = (const float*)d_in[1];
    const float* partial = (const float*)d_in[2];
    const float* mu      = (const float*)d_in[3];
    const float* logvar  = (const float*)d_in[4];
    float* out = (float*)d_out;

    float *pf, *fp, *pp;
    cudaGetSymbolAddress((void**)&pf, g_pf);
    cudaGetSymbolAddress((void**)&fp, g_fp);
    cudaGetSymbolAddress((void**)&pp, g_part);

    // Init mins to 0x7f7f7f7f (3.39e38 > any real squared distance) via
    // byte-pattern memset — graph-capturable, no extra kernel launch.
    cudaMemsetAsync(pf, 0x7f, BB * NFULL * sizeof(float));
    cudaMemsetAsync(fp, 0x7f, BB * NFULL * sizeof(float));
    cudaMemsetAsync(pp, 0x7f, BB * NPART * sizeof(float));

    fused_rowmin_kernel<<<TOT_BLKS, THREADS>>>(pred, full, partial, pf, fp, pp);

    reduce_kernel<<<1, 1024>>>(pf, fp, pp, mu, logvar, out);
}

// round 4
// speedup vs baseline: 1.2067x; 1.2067x over previous
#include <cuda_runtime.h>
#include <math.h>

#define BB     8
#define NFULL  8192
#define NPART  2048
#define DLAT   512
#define EPSV   1e-12f

__device__ float g_pf[BB * NFULL];
__device__ float g_fp[BB * NFULL];
__device__ float g_part[BB * NPART];

constexpr int RBLKS = 120;                 // stage-1 reduce blocks
__device__ float g_partial[4 * RBLKS];     // [pf, fp, pp, kl] x block

constexpr int THREADS = 256;
constexpr int Q       = 4;                // queries per thread
constexpr int QPB     = THREADS * Q;      // 1024
constexpr int CHUNK   = 2048;             // ref points per tile
constexpr int CH2     = CHUNK / 2;        // packed ref pairs per tile

typedef unsigned long long u64;

__device__ __forceinline__ u64 pack2(float lo, float hi) {
    u64 r; asm("mov.b64 %0, {%1, %2};" : "=l"(r) : "f"(lo), "f"(hi)); return r;
}
__device__ __forceinline__ void unpack2(u64 v, float& lo, float& hi) {
    asm("mov.b64 {%0, %1}, %2;" : "=f"(lo), "=f"(hi) : "l"(v));
}
__device__ __forceinline__ u64 ffma2(u64 a, u64 b, u64 c) {
    u64 d; asm("fma.rn.f32x2 %0, %1, %2, %3;" : "=l"(d) : "l"(a), "l"(b), "l"(c)); return d;
}

// ---------------------------------------------------------------------------
// Fused row-min (unchanged from R3: ~140us, near FFMA2 pipe floor)
// ---------------------------------------------------------------------------
constexpr int RCHUNKS   = NFULL / CHUNK;            // 4
constexpr int CHAM_QT   = NFULL / QPB;              // 8
constexpr int FID_QT    = NPART / QPB;              // 2
constexpr int CHAM_BLKS = CHAM_QT * RCHUNKS * BB;   // 256
constexpr int FID_BLKS  = FID_QT * RCHUNKS * BB;    // 64
constexpr int TOT_BLKS  = 2 * CHAM_BLKS + FID_BLKS; // 576

__global__ __launch_bounds__(THREADS)
void fused_rowmin_kernel(const float* __restrict__ pred,
                         const float* __restrict__ full,
                         const float* __restrict__ partial,
                         float* __restrict__ pf,
                         float* __restrict__ fp,
                         float* __restrict__ pp) {
    __shared__ ulonglong2 tA[CH2];   // (.x = pack(x0,x1), .y = pack(y0,y1))
    __shared__ ulonglong2 tB[CH2];   // (.x = pack(z0,z1), .y = pack(w0,w1))

    const float *q, *r;
    float* outmin;
    int Nq, qtiles, l = blockIdx.x;
    if (l < CHAM_BLKS) {
        q = pred; r = full; outmin = pf; Nq = NFULL; qtiles = CHAM_QT;
    } else if (l < 2 * CHAM_BLKS) {
        l -= CHAM_BLKS;
        q = full; r = pred; outmin = fp; Nq = NFULL; qtiles = CHAM_QT;
    } else {
        l -= 2 * CHAM_BLKS;
        q = partial; r = pred; outmin = pp; Nq = NPART; qtiles = FID_QT;
    }
    const int b  = l / (qtiles * RCHUNKS);
    const int rm = l % (qtiles * RCHUNKS);
    const int ck = rm / qtiles;
    const int qt = rm % qtiles;
    const int qbase = qt * QPB;
    const int rbase = ck * CHUNK;

    const float* qb = q + (size_t)b * Nq * 3;
    const float* rb = r + (size_t)b * NFULL * 3;

    for (int j = threadIdx.x; j < CH2; j += THREADS) {
        int rj = rbase + 2 * j;
        float x0 = rb[rj * 3 + 0], y0 = rb[rj * 3 + 1], z0 = rb[rj * 3 + 2];
        float x1 = rb[rj * 3 + 3], y1 = rb[rj * 3 + 4], z1 = rb[rj * 3 + 5];
        float w0 = 0.5f * (x0 * x0 + y0 * y0 + z0 * z0);
        float w1 = 0.5f * (x1 * x1 + y1 * y1 + z1 * z1);
        ulonglong2 a, bb;
        a.x  = pack2(x0, x1); a.y  = pack2(y0, y1);
        bb.x = pack2(z0, z1); bb.y = pack2(w0, w1);
        tA[j] = a;
        tB[j] = bb;
    }
    __syncthreads();

    u64 nqx[Q], nqy[Q], nqz[Q];
    float q2[Q], m0[Q], m1[Q];
#pragma unroll
    for (int k = 0; k < Q; k++) {
        int qi = qbase + threadIdx.x + k * THREADS;
        float x = qb[qi * 3 + 0];
        float y = qb[qi * 3 + 1];
        float z = qb[qi * 3 + 2];
        nqx[k] = pack2(-x, -x);
        nqy[k] = pack2(-y, -y);
        nqz[k] = pack2(-z, -z);
        q2[k]  = x * x + y * y + z * z;
        m0[k]  = __int_as_float(0x7f800000);
        m1[k]  = __int_as_float(0x7f800000);
    }

#pragma unroll 4
    for (int j = 0; j < CH2; j++) {
        ulonglong2 A = tA[j];
        ulonglong2 B = tB[j];
#pragma unroll
        for (int k = 0; k < Q; k++) {
            u64 v = ffma2(nqz[k], B.x, B.y);
            v = ffma2(nqy[k], A.y, v);
            v = ffma2(nqx[k], A.x, v);
            float v0, v1;
            unpack2(v, v0, v1);
            m0[k] = fminf(m0[k], v0);
            m1[k] = fminf(m1[k], v1);
        }
    }

#pragma unroll
    for (int k = 0; k < Q; k++) {
        int qi   = qbase + threadIdx.x + k * THREADS;
        float mn = fminf(m0[k], m1[k]);
        float sq = fmaf(2.0f, mn, q2[k]);
        float v  = fmaxf(sq, EPSV);
        atomicMin((unsigned int*)&outmin[(size_t)b * Nq + qi], __float_as_uint(v));
    }
}

// ---------------------------------------------------------------------------
// Stage-1 reduce: RBLKS blocks grid-stride all four sums; deterministic
// per-block partials to fixed slots.
// ---------------------------------------------------------------------------
__global__ __launch_bounds__(256)
void reduce1_kernel(const float* __restrict__ pf,
                    const float* __restrict__ fp,
                    const float* __restrict__ pp,
                    const float* __restrict__ mu,
                    const float* __restrict__ lv,
                    float* __restrict__ partials) {
    const int tid    = threadIdx.x;
    const int stride = gridDim.x * blockDim.x;
    const int g      = blockIdx.x * blockDim.x + tid;

    float s_pf = 0.f, s_fp = 0.f, s_pp = 0.f, s_kl = 0.f;
    for (int i = g; i < BB * NFULL; i += stride) {
        s_pf += sqrtf(pf[i]);
        s_fp += sqrtf(fp[i]);
    }
    for (int i = g; i < BB * NPART; i += stride) s_pp += sqrtf(pp[i]);
    for (int i = g; i < BB * DLAT; i += stride) {
        float m = mu[i], l = lv[i];
        s_kl += 1.0f + l - m * m - expf(l);
    }

    __shared__ float sh[4][8];
#pragma unroll
    for (int off = 16; off > 0; off >>= 1) {
        s_pf += __shfl_down_sync(0xffffffffu, s_pf, off);
        s_fp += __shfl_down_sync(0xffffffffu, s_fp, off);
        s_pp += __shfl_down_sync(0xffffffffu, s_pp, off);
        s_kl += __shfl_down_sync(0xffffffffu, s_kl, off);
    }
    int wid = tid >> 5, lid = tid & 31;
    if (lid == 0) { sh[0][wid] = s_pf; sh[1][wid] = s_fp; sh[2][wid] = s_pp; sh[3][wid] = s_kl; }
    __syncthreads();

    if (tid < 4) {
        float acc = 0.f;
#pragma unroll
        for (int w = 0; w < 8; w++) acc += sh[tid][w];
        partials[tid * RBLKS + blockIdx.x] = acc;
    }
}

// ---------------------------------------------------------------------------
// Stage-2 reduce: fold RBLKS partials per quantity, emit outputs.
// ---------------------------------------------------------------------------
__global__ __launch_bounds__(128)
void reduce2_kernel(const float* __restrict__ partials,
                    float* __restrict__ out) {
    const int tid = threadIdx.x;
    const int wid = tid >> 5;   // 0..3 -> quantity
    const int lid = tid & 31;

    float s = 0.f;
    for (int i = lid; i < RBLKS; i += 32) s += partials[wid * RBLKS + i];
#pragma unroll
    for (int off = 16; off > 0; off >>= 1)
        s += __shfl_down_sync(0xffffffffu, s, off);

    __shared__ float sums[4];
    if (lid == 0) sums[wid] = s;
    __syncthreads();

    if (tid == 0) {
        float inv_nf = 1.0f / (float)(BB * NFULL);
        float cd  = 0.5f * (sums[0] + sums[1]) * inv_nf;
        float fid = sums[2] / (float)(BB * NPART);
        float kl  = -0.5f * sums[3] / (float)BB;
        float total = 1.0f * cd + 0.01f * kl + 0.5f * fid;
        out[0] = total;
        out[1] = cd;
        out[2] = kl;
        out[3] = fid;
    }
}

// ---------------------------------------------------------------------------
extern "C" void kernel_launch(void* const* d_in, const int* in_sizes, int n_in,
                              void* d_out, int out_size) {
    const float* pred    = (const float*)d_in[0];
    const float* full    = (const float*)d_in[1];
    const float* partial = (const float*)d_in[2];
    const float* mu      = (const float*)d_in[3];
    const float* logvar  = (const float*)d_in[4];
    float* out = (float*)d_out;

    float *pf, *fp, *pp, *pt;
    cudaGetSymbolAddress((void**)&pf, g_pf);
    cudaGetSymbolAddress((void**)&fp, g_fp);
    cudaGetSymbolAddress((void**)&pp, g_part);
    cudaGetSymbolAddress((void**)&pt, g_partial);

    // Init mins to 0x7f7f7f7f (3.39e38 > any real squared distance).
    cudaMemsetAsync(pf, 0x7f, BB * NFULL * sizeof(float));
    cudaMemsetAsync(fp, 0x7f, BB * NFULL * sizeof(float));
    cudaMemsetAsync(pp, 0x7f, BB * NPART * sizeof(float));

    fused_rowmin_kernel<<<TOT_BLKS, THREADS>>>(pred, full, partial, pf, fp, pp);

    reduce1_kernel<<<RBLKS, 256>>>(pf, fp, pp, mu, logvar, pt);
    reduce2_kernel<<<1, 128>>>(pt, out);
}

// round 5
// speedup vs baseline: 1.2364x; 1.0246x over previous
#include <cuda_runtime.h>
#include <math.h>

#define BB     8
#define NFULL  8192
#define NPART  2048
#define DLAT   512
#define EPSV   1e-12f

__device__ float g_pf[BB * NFULL];
__device__ float g_fp[BB * NFULL];
__device__ float g_part[BB * NPART];

constexpr int RBLKS = 120;                 // stage-1 reduce blocks
__device__ float g_partial[4 * RBLKS];     // [pf, fp, pp, kl] x block

constexpr int THREADS = 256;
constexpr int Q       = 4;                // queries per thread
constexpr int QPB     = THREADS * Q;      // 1024
constexpr int CHUNK   = 1024;             // ref points per tile (16.5KB smem)
constexpr int CH2     = CHUNK / 2;        // packed ref pairs per tile

typedef unsigned long long u64;

__device__ __forceinline__ u64 pack2(float lo, float hi) {
    u64 r; asm("mov.b64 %0, {%1, %2};" : "=l"(r) : "f"(lo), "f"(hi)); return r;
}
__device__ __forceinline__ void unpack2(u64 v, float& lo, float& hi) {
    asm("mov.b64 {%0, %1}, %2;" : "=f"(lo), "=f"(hi) : "l"(v));
}
__device__ __forceinline__ u64 ffma2(u64 a, u64 b, u64 c) {
    u64 d; asm("fma.rn.f32x2 %0, %1, %2, %3;" : "=l"(d) : "l"(a), "l"(b), "l"(c)); return d;
}

// ---------------------------------------------------------------------------
// Fused row-min: chamfer pred->full, full->pred, fidelity partial->pred.
// min_j( w_j - dot(q, r_j) ), w = |r|^2/2; sq = q^2 + 2*min.
// CHUNK=1024 -> 1152 blocks -> ~6 resident blocks/SM (48 warps) for issue hiding.
// ---------------------------------------------------------------------------
constexpr int RCHUNKS   = NFULL / CHUNK;            // 8
constexpr int CHAM_QT   = NFULL / QPB;              // 8
constexpr int FID_QT    = NPART / QPB;              // 2
constexpr int CHAM_BLKS = CHAM_QT * RCHUNKS * BB;   // 512
constexpr int FID_BLKS  = FID_QT * RCHUNKS * BB;    // 128
constexpr int TOT_BLKS  = 2 * CHAM_BLKS + FID_BLKS; // 1152

__global__ __launch_bounds__(THREADS)
void fused_rowmin_kernel(const float* __restrict__ pred,
                         const float* __restrict__ full,
                         const float* __restrict__ partial,
                         float* __restrict__ pf,
                         float* __restrict__ fp,
                         float* __restrict__ pp) {
    __shared__ ulonglong2 tA[CH2];   // (.x = pack(x0,x1), .y = pack(y0,y1))
    __shared__ ulonglong2 tB[CH2];   // (.x = pack(z0,z1), .y = pack(w0,w1))

    const float *q, *r;
    float* outmin;
    int Nq, qtiles, l = blockIdx.x;
    if (l < CHAM_BLKS) {
        q = pred; r = full; outmin = pf; Nq = NFULL; qtiles = CHAM_QT;
    } else if (l < 2 * CHAM_BLKS) {
        l -= CHAM_BLKS;
        q = full; r = pred; outmin = fp; Nq = NFULL; qtiles = CHAM_QT;
    } else {
        l -= 2 * CHAM_BLKS;
        q = partial; r = pred; outmin = pp; Nq = NPART; qtiles = FID_QT;
    }
    const int b  = l / (qtiles * RCHUNKS);
    const int rm = l % (qtiles * RCHUNKS);
    const int ck = rm / qtiles;
    const int qt = rm % qtiles;
    const int qbase = qt * QPB;
    const int rbase = ck * CHUNK;

    const float* qb = q + (size_t)b * Nq * 3;
    const float* rb = r + (size_t)b * NFULL * 3;

    for (int j = threadIdx.x; j < CH2; j += THREADS) {
        int rj = rbase + 2 * j;
        float x0 = rb[rj * 3 + 0], y0 = rb[rj * 3 + 1], z0 = rb[rj * 3 + 2];
        float x1 = rb[rj * 3 + 3], y1 = rb[rj * 3 + 4], z1 = rb[rj * 3 + 5];
        float w0 = 0.5f * (x0 * x0 + y0 * y0 + z0 * z0);
        float w1 = 0.5f * (x1 * x1 + y1 * y1 + z1 * z1);
        ulonglong2 a, bb;
        a.x  = pack2(x0, x1); a.y  = pack2(y0, y1);
        bb.x = pack2(z0, z1); bb.y = pack2(w0, w1);
        tA[j] = a;
        tB[j] = bb;
    }
    __syncthreads();

    u64 nqx[Q], nqy[Q], nqz[Q];
    float q2[Q], m0[Q], m1[Q];
#pragma unroll
    for (int k = 0; k < Q; k++) {
        int qi = qbase + threadIdx.x + k * THREADS;
        float x = qb[qi * 3 + 0];
        float y = qb[qi * 3 + 1];
        float z = qb[qi * 3 + 2];
        nqx[k] = pack2(-x, -x);
        nqy[k] = pack2(-y, -y);
        nqz[k] = pack2(-z, -z);
        q2[k]  = x * x + y * y + z * z;
        m0[k]  = __int_as_float(0x7f800000);
        m1[k]  = __int_as_float(0x7f800000);
    }

#pragma unroll 4
    for (int j = 0; j < CH2; j++) {
        ulonglong2 A = tA[j];
        ulonglong2 B = tB[j];
#pragma unroll
        for (int k = 0; k < Q; k++) {
            u64 v = ffma2(nqz[k], B.x, B.y);
            v = ffma2(nqy[k], A.y, v);
            v = ffma2(nqx[k], A.x, v);
            float v0, v1;
            unpack2(v, v0, v1);
            m0[k] = fminf(m0[k], v0);
            m1[k] = fminf(m1[k], v1);
        }
    }

#pragma unroll
    for (int k = 0; k < Q; k++) {
        int qi   = qbase + threadIdx.x + k * THREADS;
        float mn = fminf(m0[k], m1[k]);
        float sq = fmaf(2.0f, mn, q2[k]);
        float v  = fmaxf(sq, EPSV);
        atomicMin((unsigned int*)&outmin[(size_t)b * Nq + qi], __float_as_uint(v));
    }
}

// ---------------------------------------------------------------------------
// Stage-1 reduce: RBLKS blocks grid-stride all four sums.
// ---------------------------------------------------------------------------
__global__ __launch_bounds__(256)
void reduce1_kernel(const float* __restrict__ pf,
                    const float* __restrict__ fp,
                    const float* __restrict__ pp,
                    const float* __restrict__ mu,
                    const float* __restrict__ lv,
                    float* __restrict__ partials) {
    const int tid    = threadIdx.x;
    const int stride = gridDim.x * blockDim.x;
    const int g      = blockIdx.x * blockDim.x + tid;

    float s_pf = 0.f, s_fp = 0.f, s_pp = 0.f, s_kl = 0.f;
    for (int i = g; i < BB * NFULL; i += stride) {
        s_pf += sqrtf(pf[i]);
        s_fp += sqrtf(fp[i]);
    }
    for (int i = g; i < BB * NPART; i += stride) s_pp += sqrtf(pp[i]);
    for (int i = g; i < BB * DLAT; i += stride) {
        float m = mu[i], l = lv[i];
        s_kl += 1.0f + l - m * m - expf(l);
    }

    __shared__ float sh[4][8];
#pragma unroll
    for (int off = 16; off > 0; off >>= 1) {
        s_pf += __shfl_down_sync(0xffffffffu, s_pf, off);
        s_fp += __shfl_down_sync(0xffffffffu, s_fp, off);
        s_pp += __shfl_down_sync(0xffffffffu, s_pp, off);
        s_kl += __shfl_down_sync(0xffffffffu, s_kl, off);
    }
    int wid = tid >> 5, lid = tid & 31;
    if (lid == 0) { sh[0][wid] = s_pf; sh[1][wid] = s_fp; sh[2][wid] = s_pp; sh[3][wid] = s_kl; }
    __syncthreads();

    if (tid < 4) {
        float acc = 0.f;
#pragma unroll
        for (int w = 0; w < 8; w++) acc += sh[tid][w];
        partials[tid * RBLKS + blockIdx.x] = acc;
    }
}

// ---------------------------------------------------------------------------
__global__ __launch_bounds__(128)
void reduce2_kernel(const float* __restrict__ partials,
                    float* __restrict__ out) {
    const int tid = threadIdx.x;
    const int wid = tid >> 5;
    const int lid = tid & 31;

    float s = 0.f;
    for (int i = lid; i < RBLKS; i += 32) s += partials[wid * RBLKS + i];
#pragma unroll
    for (int off = 16; off > 0; off >>= 1)
        s += __shfl_down_sync(0xffffffffu, s, off);

    __shared__ float sums[4];
    if (lid == 0) sums[wid] = s;
    __syncthreads();

    if (tid == 0) {
        float inv_nf = 1.0f / (float)(BB * NFULL);
        float cd  = 0.5f * (sums[0] + sums[1]) * inv_nf;
        float fid = sums[2] / (float)(BB * NPART);
        float kl  = -0.5f * sums[3] / (float)BB;
        float total = 1.0f * cd + 0.01f * kl + 0.5f * fid;
        out[0] = total;
        out[1] = cd;
        out[2] = kl;
        out[3] = fid;
    }
}

// ---------------------------------------------------------------------------
extern "C" void kernel_launch(void* const* d_in, const int* in_sizes, int n_in,
                              void* d_out, int out_size) {
    const float* pred    = (const float*)d_in[0];
    const float* full    = (const float*)d_in[1];
    const float* partial = (const float*)d_in[2];
    const float* mu      = (const float*)d_in[3];
    const float* logvar  = (const float*)d_in[4];
    float* out = (float*)d_out;

    float *pf, *fp, *pp, *pt;
    cudaGetSymbolAddress((void**)&pf, g_pf);
    cudaGetSymbolAddress((void**)&fp, g_fp);
    cudaGetSymbolAddress((void**)&pp, g_part);
    cudaGetSymbolAddress((void**)&pt, g_partial);

    // Init mins to 0x7f7f7f7f (3.39e38 > any real squared distance).
    cudaMemsetAsync(pf, 0x7f, BB * NFULL * sizeof(float));
    cudaMemsetAsync(fp, 0x7f, BB * NFULL * sizeof(float));
    cudaMemsetAsync(pp, 0x7f, BB * NPART * sizeof(float));

    fused_rowmin_kernel<<<TOT_BLKS, THREADS>>>(pred, full, partial, pf, fp, pp);

    reduce1_kernel<<<RBLKS, 256>>>(pf, fp, pp, mu, logvar, pt);
    reduce2_kernel<<<1, 128>>>(pt, out);
}